// round 5
// baseline (speedup 1.0000x reference)
#include <cuda_runtime.h>
#include <stdint.h>

#define NN 100000
#define NE 800000
#define C  100
#define OC 50
#define NBLK ((NN + 1023) / 1024)

#define TM 128                 // gemm row tile
#define NTILES ((NN + TM - 1) / TM)
#define GEMM_GRID 148
#define GEMM_THREADS 256

// smem float offsets (stride-108 padding -> conflict-free frag loads)
#define AS 108
#define BS 108
#define AHI 0
#define ALO (128 * AS)
#define BHI (2 * 128 * AS)
#define BLO (BHI + 104 * BS)
#define SM_FLOATS (BLO + 104 * BS)
#define SMEM_DYN (SM_FLOATS * 4)

// ---------------- device globals (scratch) ----------------
__device__ __align__(16) float d_dis[NN];
__device__ __align__(16) float d_G[NN * C];
__device__ __align__(16) float d_H[NN * C];
__device__ int d_cnt[NN];
__device__ int d_start[NN];      // scan result; k_fill mutates it into END pointers
__device__ int d_csr[NE];
__device__ int d_bsum[NBLK + 1];
__device__ int d_boff[NBLK + 1];

// ---------------- mma helpers (baseline PTX, sm_80+) ----------------
__device__ __forceinline__ uint32_t f2tf32(float x) {
    uint32_t r;
    asm("cvt.rna.tf32.f32 %0, %1;" : "=r"(r) : "f"(x));
    return r;
}
__device__ __forceinline__ void mma_tf32(float* d, const uint32_t* a, const uint32_t* b) {
    asm volatile(
        "mma.sync.aligned.m16n8k8.row.col.f32.tf32.tf32.f32 "
        "{%0,%1,%2,%3}, {%4,%5,%6,%7}, {%8,%9}, {%0,%1,%2,%3};"
        : "+f"(d[0]), "+f"(d[1]), "+f"(d[2]), "+f"(d[3])
        : "r"(a[0]), "r"(a[1]), "r"(a[2]), "r"(a[3]), "r"(b[0]), "r"(b[1]));
}

// ---------------- CSR build ----------------
__global__ void k_zero() {
    int i = blockIdx.x * blockDim.x + threadIdx.x;
    if (i < NN) d_cnt[i] = 0;
}
__global__ void k_deg(const int* __restrict__ dst) {
    int e = blockIdx.x * blockDim.x + threadIdx.x;
    if (e < NE) atomicAdd(&d_cnt[dst[e]], 1);
}
__global__ void k_scan1() {   // block-local exclusive scan + dis = rsqrt(cnt+1)
    __shared__ int sh[1024];
    int i = blockIdx.x * 1024 + threadIdx.x;
    int v = (i < NN) ? d_cnt[i] : 0;
    sh[threadIdx.x] = v;
    __syncthreads();
    for (int off = 1; off < 1024; off <<= 1) {
        int t = (threadIdx.x >= off) ? sh[threadIdx.x - off] : 0;
        __syncthreads();
        sh[threadIdx.x] += t;
        __syncthreads();
    }
    if (i < NN) {
        d_start[i] = sh[threadIdx.x] - v;
        d_dis[i] = rsqrtf((float)v + 1.0f);
    }
    if (threadIdx.x == 1023) d_bsum[blockIdx.x] = sh[1023];
}
__global__ void k_scan2() {
    __shared__ int sh[128];
    int t = threadIdx.x;
    int v = (t < NBLK) ? d_bsum[t] : 0;
    sh[t] = v;
    __syncthreads();
    for (int off = 1; off < 128; off <<= 1) {
        int u = (t >= off) ? sh[t - off] : 0;
        __syncthreads();
        sh[t] += u;
        __syncthreads();
    }
    if (t < NBLK) d_boff[t] = sh[t] - v;
}
__global__ void k_scan3() {
    int i = blockIdx.x * blockDim.x + threadIdx.x;
    if (i < NN) d_start[i] += d_boff[i >> 10];
}
// p = atomicAdd(start[d],1): start[] becomes END pointers; gather uses end-cnt.
__global__ void k_fill(const int* __restrict__ src, const int* __restrict__ dst) {
    int e = blockIdx.x * blockDim.x + threadIdx.x;
    if (e >= NE) return;
    int d = dst[e];
    int p = atomicAdd(&d_start[d], 1);
    d_csr[p] = src[e];
}

// ---------------- 3xTF32 tensor-core GEMM: G = dis[row] * (A @ W) ----------------
__global__ void __launch_bounds__(GEMM_THREADS, 1)
k_gemm_tc(const float* __restrict__ Ain, const float* __restrict__ W0,
          const float* __restrict__ Wa, const float* __restrict__ Wb, int mode) {
    extern __shared__ uint32_t sm[];
    const float* A = (mode == 0) ? Ain : d_H;
    const int tid = threadIdx.x, wid = tid >> 5, lane = tid & 31;
    const int g = lane >> 2, tg = lane & 3;

    for (int i = tid; i < SM_FLOATS; i += GEMM_THREADS) sm[i] = 0;
    __syncthreads();

    for (int idx = tid; idx < C * C; idx += GEMM_THREADS) {
        int k = idx / C, n = idx % C;
        float w = (mode == 0) ? W0[idx]
                              : ((n < OC) ? Wa[k * OC + n] : Wb[k * OC + (n - OC)]);
        uint32_t hi = f2tf32(w);
        uint32_t lo = f2tf32(w - __uint_as_float(hi));
        sm[BHI + k * BS + n] = hi;
        sm[BLO + k * BS + n] = lo;
    }
    __syncthreads();

    const int r0 = wid * 16;

    for (int t = blockIdx.x; t < NTILES; t += gridDim.x) {
        const int i0 = t * TM;
        const int rowlim = NN - i0;

        for (int q = tid; q < TM * 25; q += GEMM_THREADS) {
            int r = q / 25, c4 = (q % 25) * 4;
            float4 v = (r < rowlim) ? *(const float4*)&A[(size_t)(i0 + r) * C + c4]
                                    : make_float4(0.f, 0.f, 0.f, 0.f);
            uint32_t hx = f2tf32(v.x), hy = f2tf32(v.y), hz = f2tf32(v.z), hw = f2tf32(v.w);
            uint32_t base = r * AS + c4;
            sm[AHI + base + 0] = hx;
            sm[AHI + base + 1] = hy;
            sm[AHI + base + 2] = hz;
            sm[AHI + base + 3] = hw;
            sm[ALO + base + 0] = f2tf32(v.x - __uint_as_float(hx));
            sm[ALO + base + 1] = f2tf32(v.y - __uint_as_float(hy));
            sm[ALO + base + 2] = f2tf32(v.z - __uint_as_float(hz));
            sm[ALO + base + 3] = f2tf32(v.w - __uint_as_float(hw));
        }
        __syncthreads();

        float acc[13][4];
        #pragma unroll
        for (int nt = 0; nt < 13; nt++)
            #pragma unroll
            for (int q = 0; q < 4; q++) acc[nt][q] = 0.f;

        #pragma unroll
        for (int kt = 0; kt < 13; kt++) {
            const int k0 = kt * 8;
            uint32_t ah[4], al[4];
            ah[0] = sm[AHI + (r0 + g) * AS + k0 + tg];
            ah[1] = sm[AHI + (r0 + g + 8) * AS + k0 + tg];
            ah[2] = sm[AHI + (r0 + g) * AS + k0 + tg + 4];
            ah[3] = sm[AHI + (r0 + g + 8) * AS + k0 + tg + 4];
            al[0] = sm[ALO + (r0 + g) * AS + k0 + tg];
            al[1] = sm[ALO + (r0 + g + 8) * AS + k0 + tg];
            al[2] = sm[ALO + (r0 + g) * AS + k0 + tg + 4];
            al[3] = sm[ALO + (r0 + g + 8) * AS + k0 + tg + 4];
            #pragma unroll
            for (int nt = 0; nt < 13; nt++) {
                const int n0 = nt * 8;
                uint32_t bh[2], bl[2];
                bh[0] = sm[BHI + (k0 + tg) * BS + n0 + g];
                bh[1] = sm[BHI + (k0 + tg + 4) * BS + n0 + g];
                bl[0] = sm[BLO + (k0 + tg) * BS + n0 + g];
                bl[1] = sm[BLO + (k0 + tg + 4) * BS + n0 + g];
                mma_tf32(acc[nt], ah, bh);
                mma_tf32(acc[nt], al, bh);
                mma_tf32(acc[nt], ah, bl);
            }
        }

        const int row1 = i0 + r0 + g, row2 = row1 + 8;
        const float s1 = (row1 < NN) ? d_dis[row1] : 0.f;
        const float s2 = (row2 < NN) ? d_dis[row2] : 0.f;
        #pragma unroll
        for (int nt = 0; nt < 13; nt++) {
            const int c = nt * 8 + 2 * tg;
            if (c < C) {
                if (row1 < NN)
                    *(float2*)&d_G[(size_t)row1 * C + c] =
                        make_float2(s1 * acc[nt][0], s1 * acc[nt][1]);
                if (row2 < NN)
                    *(float2*)&d_G[(size_t)row2 * C + c] =
                        make_float2(s2 * acc[nt][2], s2 * acc[nt][3]);
            }
        }
        __syncthreads();
    }
}

// ---------------- gather + epilogues (4x unrolled for MLP) ----------------
__global__ void k_gather(int mode, const float* __restrict__ b1,
                         const float* __restrict__ bmu, const float* __restrict__ bls,
                         float* __restrict__ out) {
    int w = (blockIdx.x * blockDim.x + threadIdx.x) >> 5;
    int lane = threadIdx.x & 31;
    if (w >= NN || lane >= 25) return;
    int en = d_start[w];          // END pointer (post-fill)
    int n  = d_cnt[w];
    int st = en - n;
    int p4 = lane * 4;

    float4 acc = *(const float4*)&d_G[(size_t)w * C + p4];   // self-loop term

    int j = 0;
    for (; j + 4 <= n; j += 4) {
        int s0 = d_csr[st + j + 0];
        int s1 = d_csr[st + j + 1];
        int s2 = d_csr[st + j + 2];
        int s3 = d_csr[st + j + 3];
        float4 g0 = *(const float4*)&d_G[(size_t)s0 * C + p4];
        float4 g1 = *(const float4*)&d_G[(size_t)s1 * C + p4];
        float4 g2 = *(const float4*)&d_G[(size_t)s2 * C + p4];
        float4 g3 = *(const float4*)&d_G[(size_t)s3 * C + p4];
        acc.x += (g0.x + g1.x) + (g2.x + g3.x);
        acc.y += (g0.y + g1.y) + (g2.y + g3.y);
        acc.z += (g0.z + g1.z) + (g2.z + g3.z);
        acc.w += (g0.w + g1.w) + (g2.w + g3.w);
    }
    for (; j < n; j++) {
        int s = d_csr[st + j];
        float4 g = *(const float4*)&d_G[(size_t)s * C + p4];
        acc.x += g.x; acc.y += g.y; acc.z += g.z; acc.w += g.w;
    }
    float sc = d_dis[w];

    if (mode == 0) {
        float4 bb = *(const float4*)&b1[p4];
        float4 h;
        h.x = fmaxf(fmaf(sc, acc.x, bb.x), 0.f);
        h.y = fmaxf(fmaf(sc, acc.y, bb.y), 0.f);
        h.z = fmaxf(fmaf(sc, acc.z, bb.z), 0.f);
        h.w = fmaxf(fmaf(sc, acc.w, bb.w), 0.f);
        *(float4*)&d_H[(size_t)w * C + p4] = h;
    } else {
        float v[4] = { sc * acc.x, sc * acc.y, sc * acc.z, sc * acc.w };
        #pragma unroll
        for (int q = 0; q < 4; q++) {
            int c = p4 + q;
            if (c < OC) out[(size_t)w * OC + c]                          = v[q] + bmu[c];
            else        out[(size_t)NN * OC + (size_t)w * OC + (c - OC)] = v[q] + bls[c - OC];
        }
    }
}

extern "C" void kernel_launch(void* const* d_in, const int* in_sizes, int n_in,
                              void* d_out, int out_size) {
    const float* x   = (const float*)d_in[0];
    const int*   ei  = (const int*)  d_in[1];
    const float* W1  = (const float*)d_in[2];
    const float* b1  = (const float*)d_in[3];
    const float* Wmu = (const float*)d_in[4];
    const float* bmu = (const float*)d_in[5];
    const float* Wls = (const float*)d_in[6];
    const float* bls = (const float*)d_in[7];
    float* out = (float*)d_out;

    const int* src = ei;
    const int* dst = ei + NE;

    cudaFuncSetAttribute(k_gemm_tc, cudaFuncAttributeMaxDynamicSharedMemorySize, SMEM_DYN);

    // CSR build (once, reused by both gathers)
    k_zero<<<(NN + 255) / 256, 256>>>();
    k_deg<<<(NE + 255) / 256, 256>>>(dst);
    k_scan1<<<NBLK, 1024>>>();
    k_scan2<<<1, 128>>>();
    k_scan3<<<(NN + 255) / 256, 256>>>();
    k_fill<<<(NE + 255) / 256, 256>>>(src, dst);

    // layer 1
    k_gemm_tc<<<GEMM_GRID, GEMM_THREADS, SMEM_DYN>>>(x, W1, nullptr, nullptr, 0);
    k_gather<<<(NN * 32 + 255) / 256, 256>>>(0, b1, nullptr, nullptr, nullptr);

    // layers 2+3 fused (mu | logstd column-concat)
    k_gemm_tc<<<GEMM_GRID, GEMM_THREADS, SMEM_DYN>>>(nullptr, nullptr, Wmu, Wls, 1);
    k_gather<<<(NN * 32 + 255) / 256, 256>>>(1, nullptr, bmu, bls, out);
}

// round 6
// speedup vs baseline: 1.5172x; 1.5172x over previous
#include <cuda_runtime.h>
#include <cuda_fp16.h>
#include <cuda_bf16.h>
#include <stdint.h>

#define NN 100000
#define NE 800000
#define C  100
#define OC 50
#define NBLK ((NN + 1023) / 1024)

#define TM 128
#define NTILES ((NN + TM - 1) / TM)
#define GEMM_GRID 148
#define GEMM_THREADS 256

// bf16 smem: words = 2 halves. stride 60 words/row -> conflict-free frags.
#define WS 60
#define AHI 0
#define ALO (128 * WS)                 // 7680
#define BHI (2 * 128 * WS)             // 15360
#define BLO (BHI + 104 * WS)           // 21600
#define SM_WORDS (BLO + 104 * WS)      // 27840
#define SMEM_DYN (SM_WORDS * 4)        // 111360 B

// ---------------- device globals (scratch) ----------------
__device__ __align__(16) float d_dis[NN];
__device__ __align__(16) __half d_G16[NN * C];
__device__ __align__(16) __half d_H16[NN * C];
__device__ int d_cnt[NN];
__device__ int d_start[NN];   // after fill: END pointers
__device__ int d_csr[NE];
__device__ int d_bsum[NBLK + 1];

// ---------------- mma helper (baseline PTX, sm_80+) ----------------
__device__ __forceinline__ void mma_bf16(float* d, const uint32_t* a, const uint32_t* b) {
    asm volatile(
        "mma.sync.aligned.m16n8k16.row.col.f32.bf16.bf16.f32 "
        "{%0,%1,%2,%3}, {%4,%5,%6,%7}, {%8,%9}, {%0,%1,%2,%3};"
        : "+f"(d[0]), "+f"(d[1]), "+f"(d[2]), "+f"(d[3])
        : "r"(a[0]), "r"(a[1]), "r"(a[2]), "r"(a[3]), "r"(b[0]), "r"(b[1]));
}
__device__ __forceinline__ uint32_t pack_bf2(__nv_bfloat16 a, __nv_bfloat16 b) {
    __nv_bfloat162 v = __halves2bfloat162(a, b);
    return *reinterpret_cast<uint32_t*>(&v);
}

// ---------------- CSR build ----------------
__global__ void k_zero() {
    int i = blockIdx.x * blockDim.x + threadIdx.x;
    if (i < NN) d_cnt[i] = 0;
}
__global__ void k_deg(const int* __restrict__ dst) {
    int e = blockIdx.x * blockDim.x + threadIdx.x;
    if (e < NE) atomicAdd(&d_cnt[dst[e]], 1);
}
__global__ void k_scan1() {   // block-local exclusive scan + dis = rsqrt(cnt+1)
    __shared__ int sh[1024];
    int i = blockIdx.x * 1024 + threadIdx.x;
    int v = (i < NN) ? d_cnt[i] : 0;
    sh[threadIdx.x] = v;
    __syncthreads();
    for (int off = 1; off < 1024; off <<= 1) {
        int t = (threadIdx.x >= off) ? sh[threadIdx.x - off] : 0;
        __syncthreads();
        sh[threadIdx.x] += t;
        __syncthreads();
    }
    if (i < NN) {
        d_start[i] = sh[threadIdx.x] - v;
        d_dis[i] = rsqrtf((float)v + 1.0f);
    }
    if (threadIdx.x == 1023) d_bsum[blockIdx.x] = sh[1023];
}
// fused scan2+scan3: every block scans the 98 partials redundantly, then applies.
__global__ void k_scan23() {
    __shared__ int sh[128];
    int t = threadIdx.x;
    sh[t] = (t < NBLK) ? d_bsum[t] : 0;
    __syncthreads();
    for (int off = 1; off < 128; off <<= 1) {
        int u = (t >= off) ? sh[t - off] : 0;
        __syncthreads();
        sh[t] += u;
        __syncthreads();
    }
    int i = blockIdx.x * 256 + (t & 0xFF);
    // 256 work items per block, 128 threads -> 2 each
    for (int q = 0; q < 2; q++) {
        int idx = blockIdx.x * 256 + q * 128 + t;
        if (idx < NN) {
            int blk = idx >> 10;
            int boff = (blk > 0) ? sh[blk - 1] : 0;
            d_start[idx] += boff;
        }
    }
    (void)i;
}
__global__ void k_fill(const int* __restrict__ src, const int* __restrict__ dst) {
    int e = blockIdx.x * blockDim.x + threadIdx.x;
    if (e >= NE) return;
    int d = dst[e];
    int p = atomicAdd(&d_start[d], 1);   // start[] becomes END pointers
    d_csr[p] = src[e];
}

// ---------------- bf16 split-3 tensor-core GEMM: G16 = dis[row]*(A @ W) ----------------
// mode 0: A = x (fp32), W = W0 [C x C]; mode 1: A = d_H16 (fp16), W = [Wa|Wb].
__global__ void __launch_bounds__(GEMM_THREADS, 1)
k_gemm_tc(const float* __restrict__ Ain, const float* __restrict__ W0,
          const float* __restrict__ Wa, const float* __restrict__ Wb, int mode) {
    extern __shared__ uint32_t sm[];
    const int tid = threadIdx.x, wid = tid >> 5, lane = tid & 31;
    const int g = lane >> 2, tg = lane & 3;

    for (int i = tid; i < SM_WORDS; i += GEMM_THREADS) sm[i] = 0;
    __syncthreads();

    // stage W -> bf16 hi/lo; layout B[n][kword], word = halves (k, k+1)
    for (int idx = tid; idx < C * C; idx += GEMM_THREADS) {
        int k = idx / C, n = idx % C;
        float w = (mode == 0) ? W0[idx]
                              : ((n < OC) ? Wa[k * OC + n] : Wb[k * OC + (n - OC)]);
        __nv_bfloat16 hi = __float2bfloat16(w);
        __nv_bfloat16 lo = __float2bfloat16(w - __bfloat162float(hi));
        ((__nv_bfloat16*)(sm + BHI))[(n * WS + (k >> 1)) * 2 + (k & 1)] = hi;
        ((__nv_bfloat16*)(sm + BLO))[(n * WS + (k >> 1)) * 2 + (k & 1)] = lo;
    }
    __syncthreads();

    const int r0 = wid * 16;

    for (int t = blockIdx.x; t < NTILES; t += gridDim.x) {
        const int i0 = t * TM;
        const int rowlim = NN - i0;

        // stage A tile [128 x 100] -> bf16 hi/lo words
        for (int q = tid; q < TM * 25; q += GEMM_THREADS) {
            int r = q / 25, c4 = (q % 25) * 4;
            float4 v;
            if (r < rowlim) {
                if (mode == 0) {
                    v = *(const float4*)&Ain[(size_t)(i0 + r) * C + c4];
                } else {
                    uint2 hraw = *(const uint2*)&d_H16[(size_t)(i0 + r) * C + c4];
                    __half2 h0 = *reinterpret_cast<__half2*>(&hraw.x);
                    __half2 h1 = *reinterpret_cast<__half2*>(&hraw.y);
                    float2 f0 = __half22float2(h0), f1 = __half22float2(h1);
                    v = make_float4(f0.x, f0.y, f1.x, f1.y);
                }
            } else {
                v = make_float4(0.f, 0.f, 0.f, 0.f);
            }
            __nv_bfloat16 hx = __float2bfloat16(v.x), hy = __float2bfloat16(v.y);
            __nv_bfloat16 hz = __float2bfloat16(v.z), hw = __float2bfloat16(v.w);
            __nv_bfloat16 lx = __float2bfloat16(v.x - __bfloat162float(hx));
            __nv_bfloat16 ly = __float2bfloat16(v.y - __bfloat162float(hy));
            __nv_bfloat16 lz = __float2bfloat16(v.z - __bfloat162float(hz));
            __nv_bfloat16 lw = __float2bfloat16(v.w - __bfloat162float(hw));
            uint32_t wbase = r * WS + (c4 >> 1);   // c4 even -> word aligned
            *(uint2*)(sm + AHI + wbase) = make_uint2(pack_bf2(hx, hy), pack_bf2(hz, hw));
            *(uint2*)(sm + ALO + wbase) = make_uint2(pack_bf2(lx, ly), pack_bf2(lz, lw));
        }
        __syncthreads();

        float acc[13][4];
        #pragma unroll
        for (int nt = 0; nt < 13; nt++)
            #pragma unroll
            for (int q = 0; q < 4; q++) acc[nt][q] = 0.f;

        #pragma unroll
        for (int kt = 0; kt < 7; kt++) {       // K = 112 (halves), 16 per step
            const int kw = kt * 8;             // word offset
            uint32_t ah[4], al[4];
            ah[0] = sm[AHI + (r0 + g) * WS + kw + tg];
            ah[1] = sm[AHI + (r0 + g + 8) * WS + kw + tg];
            ah[2] = sm[AHI + (r0 + g) * WS + kw + 4 + tg];
            ah[3] = sm[AHI + (r0 + g + 8) * WS + kw + 4 + tg];
            al[0] = sm[ALO + (r0 + g) * WS + kw + tg];
            al[1] = sm[ALO + (r0 + g + 8) * WS + kw + tg];
            al[2] = sm[ALO + (r0 + g) * WS + kw + 4 + tg];
            al[3] = sm[ALO + (r0 + g + 8) * WS + kw + 4 + tg];
            #pragma unroll
            for (int nt = 0; nt < 13; nt++) {
                const int n0 = nt * 8;
                uint32_t bh[2], bl[2];
                bh[0] = sm[BHI + (n0 + g) * WS + kw + tg];
                bh[1] = sm[BHI + (n0 + g) * WS + kw + 4 + tg];
                bl[0] = sm[BLO + (n0 + g) * WS + kw + tg];
                bl[1] = sm[BLO + (n0 + g) * WS + kw + 4 + tg];
                mma_bf16(acc[nt], ah, bh);   // hi*hi
                mma_bf16(acc[nt], al, bh);   // lo*hi
                mma_bf16(acc[nt], ah, bl);   // hi*lo
            }
        }

        // epilogue: scale by dis, store fp16 G
        const int row1 = i0 + r0 + g, row2 = row1 + 8;
        const float s1 = (row1 < NN) ? d_dis[row1] : 0.f;
        const float s2 = (row2 < NN) ? d_dis[row2] : 0.f;
        #pragma unroll
        for (int nt = 0; nt < 13; nt++) {
            const int c = nt * 8 + 2 * tg;
            if (c < C) {
                if (row1 < NN) {
                    __half2 h = __floats2half2_rn(s1 * acc[nt][0], s1 * acc[nt][1]);
                    *(__half2*)&d_G16[(size_t)row1 * C + c] = h;
                }
                if (row2 < NN) {
                    __half2 h = __floats2half2_rn(s2 * acc[nt][2], s2 * acc[nt][3]);
                    *(__half2*)&d_G16[(size_t)row2 * C + c] = h;
                }
            }
        }
        __syncthreads();
    }
}

// ---------------- gather + epilogues (fp16 G, fp32 accumulate) ----------------
__device__ __forceinline__ float4 ldg_h4(const __half* p) {
    uint2 r = *(const uint2*)p;
    __half2 a = *reinterpret_cast<__half2*>(&r.x);
    __half2 b = *reinterpret_cast<__half2*>(&r.y);
    float2 f0 = __half22float2(a), f1 = __half22float2(b);
    return make_float4(f0.x, f0.y, f1.x, f1.y);
}

__global__ void k_gather(int mode, const float* __restrict__ b1,
                         const float* __restrict__ bmu, const float* __restrict__ bls,
                         float* __restrict__ out) {
    int w = (blockIdx.x * blockDim.x + threadIdx.x) >> 5;
    int lane = threadIdx.x & 31;
    if (w >= NN || lane >= 25) return;
    int en = d_start[w];
    int n  = d_cnt[w];
    int st = en - n;
    int p4 = lane * 4;

    float4 acc = ldg_h4(&d_G16[(size_t)w * C + p4]);   // self-loop term
    for (int j = 0; j < n; j++) {
        int s = d_csr[st + j];
        float4 v = ldg_h4(&d_G16[(size_t)s * C + p4]);
        acc.x += v.x; acc.y += v.y; acc.z += v.z; acc.w += v.w;
    }
    float sc = d_dis[w];

    if (mode == 0) {
        float4 bb = *(const float4*)&b1[p4];
        __half2 h0 = __floats2half2_rn(fmaxf(fmaf(sc, acc.x, bb.x), 0.f),
                                       fmaxf(fmaf(sc, acc.y, bb.y), 0.f));
        __half2 h1 = __floats2half2_rn(fmaxf(fmaf(sc, acc.z, bb.z), 0.f),
                                       fmaxf(fmaf(sc, acc.w, bb.w), 0.f));
        uint2 packed;
        packed.x = *reinterpret_cast<uint32_t*>(&h0);
        packed.y = *reinterpret_cast<uint32_t*>(&h1);
        *(uint2*)&d_H16[(size_t)w * C + p4] = packed;
    } else {
        float v[4] = { sc * acc.x, sc * acc.y, sc * acc.z, sc * acc.w };
        #pragma unroll
        for (int q = 0; q < 4; q++) {
            int c = p4 + q;
            if (c < OC) out[(size_t)w * OC + c]                          = v[q] + bmu[c];
            else        out[(size_t)NN * OC + (size_t)w * OC + (c - OC)] = v[q] + bls[c - OC];
        }
    }
}

extern "C" void kernel_launch(void* const* d_in, const int* in_sizes, int n_in,
                              void* d_out, int out_size) {
    const float* x   = (const float*)d_in[0];
    const int*   ei  = (const int*)  d_in[1];
    const float* W1  = (const float*)d_in[2];
    const float* b1  = (const float*)d_in[3];
    const float* Wmu = (const float*)d_in[4];
    const float* bmu = (const float*)d_in[5];
    const float* Wls = (const float*)d_in[6];
    const float* bls = (const float*)d_in[7];
    float* out = (float*)d_out;

    const int* src = ei;
    const int* dst = ei + NE;

    cudaFuncSetAttribute(k_gemm_tc, cudaFuncAttributeMaxDynamicSharedMemorySize, SMEM_DYN);

    // CSR build
    k_zero<<<(NN + 255) / 256, 256>>>();
    k_deg<<<(NE + 255) / 256, 256>>>(dst);
    k_scan1<<<NBLK, 1024>>>();
    k_scan23<<<(NN + 255) / 256, 128>>>();
    k_fill<<<(NE + 255) / 256, 256>>>(src, dst);

    // layer 1
    k_gemm_tc<<<GEMM_GRID, GEMM_THREADS, SMEM_DYN>>>(x, W1, nullptr, nullptr, 0);
    k_gather<<<(NN * 32 + 255) / 256, 256>>>(0, b1, nullptr, nullptr, nullptr);

    // layers 2+3 fused (mu | logstd column-concat)
    k_gemm_tc<<<GEMM_GRID, GEMM_THREADS, SMEM_DYN>>>(nullptr, nullptr, Wmu, Wls, 1);
    k_gather<<<(NN * 32 + 255) / 256, 256>>>(1, nullptr, bmu, bls, out);
}